// round 5
// baseline (speedup 1.0000x reference)
#include <cuda_runtime.h>
#include <math.h>

// Problem constants
#define B_  1024
#define T_  256
#define I_  153
#define H_  128
#define G_  384           // 3*H
#define BT_ (B_ * T_)

// ---------------------------------------------------------------------------
// Scratch (static device globals; no runtime allocation allowed)
// ---------------------------------------------------------------------------
__device__ float g_gi[(size_t)BT_ * G_];    // gate input projections (reused for both layers)
__device__ float g_seq[(size_t)BT_ * H_];   // layer-0 output sequence
__device__ float g_hlast[B_ * H_];          // layer-1 final hidden state

typedef unsigned long long u64;

// ---------------------------------------------------------------------------
// Packed f32x2 helpers (Blackwell sm_103a): 2 fp32 FMAs per instruction
// ---------------------------------------------------------------------------
__device__ __forceinline__ u64 pack2(float lo, float hi) {
    u64 r;
    asm("mov.b64 %0, {%1, %2};" : "=l"(r) : "f"(lo), "f"(hi));
    return r;
}
__device__ __forceinline__ void unpack2(u64 v, float& lo, float& hi) {
    asm("mov.b64 {%0, %1}, %2;" : "=f"(lo), "=f"(hi) : "l"(v));
}
__device__ __forceinline__ u64 ffma2(u64 a, u64 b, u64 c) {
    u64 d;
    asm("fma.rn.f32x2 %0, %1, %2, %3;" : "=l"(d) : "l"(a), "l"(b), "l"(c));
    return d;
}

__device__ __forceinline__ float sigmoidf_fast(float x) {
    return 1.0f / (1.0f + __expf(-x));
}
__device__ __forceinline__ float tanhf_fast(float x) {
    // tanh(x) = 2/(1+e^{-2x}) - 1 ; graceful saturation at |x| large
    return fmaf(2.0f, 1.0f / (1.0f + __expf(-2.0f * x)), -1.0f);
}

// ---------------------------------------------------------------------------
// GEMM with bias: C[M,N] = A[M,K] @ W[N,K]^T + bias[N]
// 128x128 tile, BK=16, double-buffered SMEM, 256 threads, 8x8 microtile
// via FFMA2 (pairs over N). M%128==0, N%128==0. K arbitrary.
// ---------------------------------------------------------------------------
#define BKG 16

__global__ __launch_bounds__(256, 2)
void sgemm_bias_kernel(const float* __restrict__ A,
                       const float* __restrict__ W,
                       const float* __restrict__ bias,
                       float* __restrict__ C,
                       int M, int N, int K) {
    __shared__ float As[2][BKG][128];
    __shared__ float Bs[2][BKG][128];

    const int bm = blockIdx.x * 128;
    const int bn = blockIdx.y * 128;
    const int tid = threadIdx.x;
    const int tx = tid & 15;       // 8 columns each
    const int ty = tid >> 4;       // 8 rows each

    const int KT = (K + BKG - 1) / BKG;

    u64 acc2[8][4] = {};           // 8 rows x 4 f32x2 pairs (=8 cols)

    // Prologue: load tile 0 into buffer 0
    #pragma unroll
    for (int i = 0; i < 8; i++) {
        int idx = tid + i * 256;           // 0..2047
        int m = idx >> 4;
        int k = idx & 15;
        As[0][k][m] = (k < K) ? A[(size_t)(bm + m) * K + k] : 0.0f;
        Bs[0][k][m] = (k < K) ? W[(size_t)(bn + m) * K + k] : 0.0f;
    }
    __syncthreads();

    int buf = 0;
    for (int kt = 0; kt < KT; kt++) {
        float a_pf[8], b_pf[8];
        const bool has_next = (kt + 1 < KT);
        if (has_next) {
            int kbase = (kt + 1) * BKG;
            #pragma unroll
            for (int i = 0; i < 8; i++) {
                int idx = tid + i * 256;
                int m = idx >> 4;
                int k = idx & 15;
                a_pf[i] = (kbase + k < K) ? A[(size_t)(bm + m) * K + kbase + k] : 0.0f;
                b_pf[i] = (kbase + k < K) ? W[(size_t)(bn + m) * K + kbase + k] : 0.0f;
            }
        }

        #pragma unroll
        for (int k = 0; k < BKG; k++) {
            float4 aLo = *reinterpret_cast<const float4*>(&As[buf][k][ty * 8]);
            float4 aHi = *reinterpret_cast<const float4*>(&As[buf][k][ty * 8 + 4]);
            float a[8] = {aLo.x, aLo.y, aLo.z, aLo.w, aHi.x, aHi.y, aHi.z, aHi.w};
            ulonglong2 b01 = *reinterpret_cast<const ulonglong2*>(&Bs[buf][k][tx * 8]);
            ulonglong2 b23 = *reinterpret_cast<const ulonglong2*>(&Bs[buf][k][tx * 8 + 4]);
            u64 bb[4] = {b01.x, b01.y, b23.x, b23.y};
            #pragma unroll
            for (int i = 0; i < 8; i++) {
                u64 ai = pack2(a[i], a[i]);
                #pragma unroll
                for (int jj = 0; jj < 4; jj++)
                    acc2[i][jj] = ffma2(ai, bb[jj], acc2[i][jj]);
            }
        }

        if (has_next) {
            #pragma unroll
            for (int i = 0; i < 8; i++) {
                int idx = tid + i * 256;
                int m = idx >> 4;
                int k = idx & 15;
                As[buf ^ 1][k][m] = a_pf[i];
                Bs[buf ^ 1][k][m] = b_pf[i];
            }
            __syncthreads();
            buf ^= 1;
        }
    }

    // Store with bias
    #pragma unroll
    for (int i = 0; i < 8; i++) {
        int m = bm + ty * 8 + i;
        size_t row = (size_t)m * N + bn + tx * 8;
        #pragma unroll
        for (int jj = 0; jj < 4; jj++) {
            float c0, c1;
            unpack2(acc2[i][jj], c0, c1);
            int n = bn + tx * 8 + jj * 2;
            C[row + jj * 2]     = c0 + bias[n];
            C[row + jj * 2 + 1] = c1 + bias[n + 1];
        }
    }
}

// ---------------------------------------------------------------------------
// GRU recurrent scan. One CTA = 8 batch rows, 128 threads (4 warps).
// Each thread owns hidden index j = tid and ALL 8 batch rows -> every weight
// LDS (128B full wavefront) feeds 8 batch FMAs. h reads are warp broadcasts.
// W_hh resident in SMEM, transposed with stride padded to 385 (conflict-free
// transpose store; coalesced global read). SMEM = 128*385*4 + 128*8*4 ~ 197KB.
// ---------------------------------------------------------------------------
#define WSTR_ (G_ + 1)
#define SCAN_SMEM ((H_ * WSTR_ + H_ * 8) * 4)

__global__ __launch_bounds__(128, 1)
void gru_scan_kernel(const float* __restrict__ gi,     // [B, T, 384]
                     const float* __restrict__ W_hh,   // [384, 128]
                     const float* __restrict__ b_hh,   // [384]
                     float* __restrict__ seq_out,      // [B, T, 128] or null
                     float* __restrict__ h_out) {      // [B, 128] or null
    extern __shared__ float sm[];
    float* Wsh = sm;                 // [128][385]: Wsh[k*385 + g]
    float* hsh = sm + H_ * WSTR_;    // [128][8]:   hsh[k*8 + b]

    const int j  = threadIdx.x;      // 0..127
    const int b0 = blockIdx.x * 8;

    // Coalesced global read, conflict-free transposed SMEM store (stride 385)
    for (int idx = j; idx < G_ * H_; idx += 128) {
        int g = idx >> 7;            // 0..383
        int k = idx & 127;
        Wsh[k * WSTR_ + g] = W_hh[idx];
    }
    #pragma unroll
    for (int q = 0; q < 8; q++) hsh[j * 8 + q] = 0.0f;

    const float br  = b_hh[j];
    const float bz  = b_hh[H_ + j];
    const float bnn = b_hh[2 * H_ + j];
    __syncthreads();

    const float* wp = Wsh + j;

    for (int t = 0; t < T_; t++) {
        // Prefetch this step's gate inputs for all 8 batch rows (coalesced over j)
        float ir[8], iz[8], inn[8];
        #pragma unroll
        for (int q = 0; q < 8; q++) {
            const float* gp = gi + ((size_t)(b0 + q) * T_ + t) * G_;
            ir[q]  = gp[j];
            iz[q]  = gp[H_ + j];
            inn[q] = gp[2 * H_ + j];
        }

        // gh = h @ W_hh^T : 3 gates x 8 batch via packed f32x2 FMAs
        u64 ar2[4] = {}, az2[4] = {}, an2[4] = {};
        #pragma unroll 4
        for (int k = 0; k < H_; k++) {
            const float* hb = hsh + k * 8;
            ulonglong2 h01 = *reinterpret_cast<const ulonglong2*>(hb);      // batch 0..3
            ulonglong2 h23 = *reinterpret_cast<const ulonglong2*>(hb + 4);  // batch 4..7
            const float* wk = wp + k * WSTR_;
            float wr = wk[0];
            float wz = wk[H_];
            float wn = wk[2 * H_];
            u64 wr2 = pack2(wr, wr);
            u64 wz2 = pack2(wz, wz);
            u64 wn2 = pack2(wn, wn);
            ar2[0] = ffma2(wr2, h01.x, ar2[0]);
            ar2[1] = ffma2(wr2, h01.y, ar2[1]);
            ar2[2] = ffma2(wr2, h23.x, ar2[2]);
            ar2[3] = ffma2(wr2, h23.y, ar2[3]);
            az2[0] = ffma2(wz2, h01.x, az2[0]);
            az2[1] = ffma2(wz2, h01.y, az2[1]);
            az2[2] = ffma2(wz2, h23.x, az2[2]);
            az2[3] = ffma2(wz2, h23.y, az2[3]);
            an2[0] = ffma2(wn2, h01.x, an2[0]);
            an2[1] = ffma2(wn2, h01.y, an2[1]);
            an2[2] = ffma2(wn2, h23.x, an2[2]);
            an2[3] = ffma2(wn2, h23.y, an2[3]);
        }
        float ar[8], az[8], an[8];
        #pragma unroll
        for (int p = 0; p < 4; p++) {
            unpack2(ar2[p], ar[2 * p], ar[2 * p + 1]);
            unpack2(az2[p], az[2 * p], az[2 * p + 1]);
            unpack2(an2[p], an[2 * p], an[2 * p + 1]);
        }

        float hold[8];
        #pragma unroll
        for (int q = 0; q < 8; q++) hold[q] = hsh[j * 8 + q];

        float hnew[8];
        #pragma unroll
        for (int q = 0; q < 8; q++) {
            float r = sigmoidf_fast(ir[q] + ar[q] + br);
            float z = sigmoidf_fast(iz[q] + az[q] + bz);
            float n = tanhf_fast(inn[q] + r * (an[q] + bnn));
            hnew[q] = (1.0f - z) * n + z * hold[q];
        }

        __syncthreads();   // all reads of old h done
        *reinterpret_cast<float4*>(hsh + j * 8)     =
            make_float4(hnew[0], hnew[1], hnew[2], hnew[3]);
        *reinterpret_cast<float4*>(hsh + j * 8 + 4) =
            make_float4(hnew[4], hnew[5], hnew[6], hnew[7]);
        if (seq_out) {
            #pragma unroll
            for (int q = 0; q < 8; q++)
                seq_out[((size_t)(b0 + q) * T_ + t) * H_ + j] = hnew[q];
        }
        __syncthreads();   // new h visible
    }

    if (h_out) {
        #pragma unroll
        for (int q = 0; q < 8; q++)
            h_out[(b0 + q) * H_ + j] = hsh[j * 8 + q];
    }
}

// ---------------------------------------------------------------------------
// Head: out[b] = sigmoid(W2 @ relu(W1 @ h[b] + b1) + b2)
// One block (64 threads) per batch row.
// ---------------------------------------------------------------------------
__global__ __launch_bounds__(64)
void head_kernel(const float* __restrict__ h,
                 const float* __restrict__ W1, const float* __restrict__ b1,
                 const float* __restrict__ W2, const float* __restrict__ b2,
                 float* __restrict__ out) {
    __shared__ float hs[128];
    __shared__ float red[2];
    const int b = blockIdx.x;
    const int tid = threadIdx.x;   // 0..63

    hs[tid]      = h[b * 128 + tid];
    hs[tid + 64] = h[b * 128 + 64 + tid];
    __syncthreads();

    float acc = b1[tid];
    #pragma unroll 8
    for (int k = 0; k < 128; k++) acc += W1[tid * 128 + k] * hs[k];
    float v = fmaxf(acc, 0.0f) * W2[tid];

    #pragma unroll
    for (int o = 16; o > 0; o >>= 1) v += __shfl_down_sync(0xffffffffu, v, o);
    if ((tid & 31) == 0) red[tid >> 5] = v;
    __syncthreads();
    if (tid == 0) {
        float s = red[0] + red[1] + b2[0];
        out[b] = 1.0f / (1.0f + expf(-s));
    }
}

// ---------------------------------------------------------------------------
// Launch
// ---------------------------------------------------------------------------
extern "C" void kernel_launch(void* const* d_in, const int* in_sizes, int n_in,
                              void* d_out, int out_size) {
    const float* x     = (const float*)d_in[0];
    const float* W_ih0 = (const float*)d_in[1];
    const float* W_hh0 = (const float*)d_in[2];
    const float* b_ih0 = (const float*)d_in[3];
    const float* b_hh0 = (const float*)d_in[4];
    const float* W_ih1 = (const float*)d_in[5];
    const float* W_hh1 = (const float*)d_in[6];
    const float* b_ih1 = (const float*)d_in[7];
    const float* b_hh1 = (const float*)d_in[8];
    const float* W1    = (const float*)d_in[9];
    const float* b1    = (const float*)d_in[10];
    const float* W2    = (const float*)d_in[11];
    const float* b2    = (const float*)d_in[12];
    float* out = (float*)d_out;

    void *gi_p, *seq_p, *hl_p;
    cudaGetSymbolAddress(&gi_p, g_gi);
    cudaGetSymbolAddress(&seq_p, g_seq);
    cudaGetSymbolAddress(&hl_p, g_hlast);
    float* gi    = (float*)gi_p;
    float* seq   = (float*)seq_p;
    float* hlast = (float*)hl_p;

    cudaFuncSetAttribute((const void*)gru_scan_kernel,
                         cudaFuncAttributeMaxDynamicSharedMemorySize, SCAN_SMEM);

    dim3 gemm_grid(BT_ / 128, G_ / 128);

    // Layer 0: input projection, then recurrent scan (produces full sequence)
    sgemm_bias_kernel<<<gemm_grid, 256>>>(x, W_ih0, b_ih0, gi, BT_, G_, I_);
    gru_scan_kernel<<<B_ / 8, 128, SCAN_SMEM>>>(gi, W_hh0, b_hh0, seq, nullptr);

    // Layer 1: input projection on layer-0 sequence, then scan (last hidden only)
    sgemm_bias_kernel<<<gemm_grid, 256>>>(seq, W_ih1, b_ih1, gi, BT_, G_, H_);
    gru_scan_kernel<<<B_ / 8, 128, SCAN_SMEM>>>(gi, W_hh1, b_hh1, nullptr, hlast);

    // Head
    head_kernel<<<B_, 64>>>(hlast, W1, b1, W2, b2, out);
}

// round 6
// speedup vs baseline: 1.0013x; 1.0013x over previous
#include <cuda_runtime.h>
#include <math.h>

// Problem constants
#define B_  1024
#define T_  256
#define I_  153
#define H_  128
#define G_  384           // 3*H
#define BT_ (B_ * T_)

// ---------------------------------------------------------------------------
// Scratch (static device globals; no runtime allocation allowed)
// ---------------------------------------------------------------------------
__device__ float g_gi[(size_t)BT_ * G_];    // gate input projections (reused for both layers)
__device__ float g_seq[(size_t)BT_ * H_];   // layer-0 output sequence
__device__ float g_hlast[B_ * H_];          // layer-1 final hidden state

typedef unsigned long long u64;

// ---------------------------------------------------------------------------
// Packed f32x2 helpers (Blackwell sm_103a): 2 fp32 FMAs per instruction
// ---------------------------------------------------------------------------
__device__ __forceinline__ u64 pack2(float lo, float hi) {
    u64 r;
    asm("mov.b64 %0, {%1, %2};" : "=l"(r) : "f"(lo), "f"(hi));
    return r;
}
__device__ __forceinline__ void unpack2(u64 v, float& lo, float& hi) {
    asm("mov.b64 {%0, %1}, %2;" : "=f"(lo), "=f"(hi) : "l"(v));
}
__device__ __forceinline__ u64 ffma2(u64 a, u64 b, u64 c) {
    u64 d;
    asm("fma.rn.f32x2 %0, %1, %2, %3;" : "=l"(d) : "l"(a), "l"(b), "l"(c));
    return d;
}

__device__ __forceinline__ float sigmoidf_fast(float x) {
    return 1.0f / (1.0f + __expf(-x));
}
__device__ __forceinline__ float tanhf_fast(float x) {
    // tanh(x) = 2/(1+e^{-2x}) - 1 ; graceful saturation at |x| large
    return fmaf(2.0f, 1.0f / (1.0f + __expf(-2.0f * x)), -1.0f);
}

// ---------------------------------------------------------------------------
// GEMM with bias: C[M,N] = A[M,K] @ W[N,K]^T + bias[N]
// 128x128 tile, BK=16, double-buffered SMEM, 256 threads, 8x8 microtile
// via FFMA2 (pairs over N). M%128==0, N%128==0. K arbitrary.
// ---------------------------------------------------------------------------
#define BKG 16

__global__ __launch_bounds__(256, 2)
void sgemm_bias_kernel(const float* __restrict__ A,
                       const float* __restrict__ W,
                       const float* __restrict__ bias,
                       float* __restrict__ C,
                       int M, int N, int K) {
    __shared__ float As[2][BKG][128];
    __shared__ float Bs[2][BKG][128];

    const int bm = blockIdx.x * 128;
    const int bn = blockIdx.y * 128;
    const int tid = threadIdx.x;
    const int tx = tid & 15;       // 8 columns each
    const int ty = tid >> 4;       // 8 rows each

    const int KT = (K + BKG - 1) / BKG;

    u64 acc2[8][4] = {};           // 8 rows x 4 f32x2 pairs (=8 cols)

    // Prologue: load tile 0 into buffer 0
    #pragma unroll
    for (int i = 0; i < 8; i++) {
        int idx = tid + i * 256;           // 0..2047
        int m = idx >> 4;
        int k = idx & 15;
        As[0][k][m] = (k < K) ? A[(size_t)(bm + m) * K + k] : 0.0f;
        Bs[0][k][m] = (k < K) ? W[(size_t)(bn + m) * K + k] : 0.0f;
    }
    __syncthreads();

    int buf = 0;
    for (int kt = 0; kt < KT; kt++) {
        float a_pf[8], b_pf[8];
        const bool has_next = (kt + 1 < KT);
        if (has_next) {
            int kbase = (kt + 1) * BKG;
            #pragma unroll
            for (int i = 0; i < 8; i++) {
                int idx = tid + i * 256;
                int m = idx >> 4;
                int k = idx & 15;
                a_pf[i] = (kbase + k < K) ? A[(size_t)(bm + m) * K + kbase + k] : 0.0f;
                b_pf[i] = (kbase + k < K) ? W[(size_t)(bn + m) * K + kbase + k] : 0.0f;
            }
        }

        #pragma unroll
        for (int k = 0; k < BKG; k++) {
            float4 aLo = *reinterpret_cast<const float4*>(&As[buf][k][ty * 8]);
            float4 aHi = *reinterpret_cast<const float4*>(&As[buf][k][ty * 8 + 4]);
            float a[8] = {aLo.x, aLo.y, aLo.z, aLo.w, aHi.x, aHi.y, aHi.z, aHi.w};
            ulonglong2 b01 = *reinterpret_cast<const ulonglong2*>(&Bs[buf][k][tx * 8]);
            ulonglong2 b23 = *reinterpret_cast<const ulonglong2*>(&Bs[buf][k][tx * 8 + 4]);
            u64 bb[4] = {b01.x, b01.y, b23.x, b23.y};
            #pragma unroll
            for (int i = 0; i < 8; i++) {
                u64 ai = pack2(a[i], a[i]);
                #pragma unroll
                for (int jj = 0; jj < 4; jj++)
                    acc2[i][jj] = ffma2(ai, bb[jj], acc2[i][jj]);
            }
        }

        if (has_next) {
            #pragma unroll
            for (int i = 0; i < 8; i++) {
                int idx = tid + i * 256;
                int m = idx >> 4;
                int k = idx & 15;
                As[buf ^ 1][k][m] = a_pf[i];
                Bs[buf ^ 1][k][m] = b_pf[i];
            }
            __syncthreads();
            buf ^= 1;
        }
    }

    // Store with bias
    #pragma unroll
    for (int i = 0; i < 8; i++) {
        int m = bm + ty * 8 + i;
        size_t row = (size_t)m * N + bn + tx * 8;
        #pragma unroll
        for (int jj = 0; jj < 4; jj++) {
            float c0, c1;
            unpack2(acc2[i][jj], c0, c1);
            int n = bn + tx * 8 + jj * 2;
            C[row + jj * 2]     = c0 + bias[n];
            C[row + jj * 2 + 1] = c1 + bias[n + 1];
        }
    }
}

// ---------------------------------------------------------------------------
// GRU recurrent scan. One CTA = 8 batch rows, 128 threads (4 warps).
// Each thread owns hidden index j = tid and ALL 8 batch rows -> every weight
// LDS (128B full wavefront) feeds 8 batch FMAs. h reads are warp broadcasts.
// W_hh resident in SMEM, transposed with stride padded to 385 (conflict-free
// transpose store; coalesced global read). SMEM = 128*385*4 + 128*8*4 ~ 197KB.
// ---------------------------------------------------------------------------
#define WSTR_ (G_ + 1)
#define SCAN_SMEM ((H_ * WSTR_ + H_ * 8) * 4)

__global__ __launch_bounds__(128, 1)
void gru_scan_kernel(const float* __restrict__ gi,     // [B, T, 384]
                     const float* __restrict__ W_hh,   // [384, 128]
                     const float* __restrict__ b_hh,   // [384]
                     float* __restrict__ seq_out,      // [B, T, 128] or null
                     float* __restrict__ h_out) {      // [B, 128] or null
    extern __shared__ float sm[];
    float* Wsh = sm;                 // [128][385]: Wsh[k*385 + g]
    float* hsh = sm + H_ * WSTR_;    // [128][8]:   hsh[k*8 + b]

    const int j  = threadIdx.x;      // 0..127
    const int b0 = blockIdx.x * 8;

    // Coalesced global read, conflict-free transposed SMEM store (stride 385)
    for (int idx = j; idx < G_ * H_; idx += 128) {
        int g = idx >> 7;            // 0..383
        int k = idx & 127;
        Wsh[k * WSTR_ + g] = W_hh[idx];
    }
    #pragma unroll
    for (int q = 0; q < 8; q++) hsh[j * 8 + q] = 0.0f;

    const float br  = b_hh[j];
    const float bz  = b_hh[H_ + j];
    const float bnn = b_hh[2 * H_ + j];
    __syncthreads();

    const float* wp = Wsh + j;

    for (int t = 0; t < T_; t++) {
        // Prefetch this step's gate inputs for all 8 batch rows (coalesced over j)
        float ir[8], iz[8], inn[8];
        #pragma unroll
        for (int q = 0; q < 8; q++) {
            const float* gp = gi + ((size_t)(b0 + q) * T_ + t) * G_;
            ir[q]  = gp[j];
            iz[q]  = gp[H_ + j];
            inn[q] = gp[2 * H_ + j];
        }

        // gh = h @ W_hh^T : 3 gates x 8 batch via packed f32x2 FMAs
        u64 ar2[4] = {}, az2[4] = {}, an2[4] = {};
        #pragma unroll 4
        for (int k = 0; k < H_; k++) {
            const float* hb = hsh + k * 8;
            ulonglong2 h01 = *reinterpret_cast<const ulonglong2*>(hb);      // batch 0..3
            ulonglong2 h23 = *reinterpret_cast<const ulonglong2*>(hb + 4);  // batch 4..7
            const float* wk = wp + k * WSTR_;
            float wr = wk[0];
            float wz = wk[H_];
            float wn = wk[2 * H_];
            u64 wr2 = pack2(wr, wr);
            u64 wz2 = pack2(wz, wz);
            u64 wn2 = pack2(wn, wn);
            ar2[0] = ffma2(wr2, h01.x, ar2[0]);
            ar2[1] = ffma2(wr2, h01.y, ar2[1]);
            ar2[2] = ffma2(wr2, h23.x, ar2[2]);
            ar2[3] = ffma2(wr2, h23.y, ar2[3]);
            az2[0] = ffma2(wz2, h01.x, az2[0]);
            az2[1] = ffma2(wz2, h01.y, az2[1]);
            az2[2] = ffma2(wz2, h23.x, az2[2]);
            az2[3] = ffma2(wz2, h23.y, az2[3]);
            an2[0] = ffma2(wn2, h01.x, an2[0]);
            an2[1] = ffma2(wn2, h01.y, an2[1]);
            an2[2] = ffma2(wn2, h23.x, an2[2]);
            an2[3] = ffma2(wn2, h23.y, an2[3]);
        }
        float ar[8], az[8], an[8];
        #pragma unroll
        for (int p = 0; p < 4; p++) {
            unpack2(ar2[p], ar[2 * p], ar[2 * p + 1]);
            unpack2(az2[p], az[2 * p], az[2 * p + 1]);
            unpack2(an2[p], an[2 * p], an[2 * p + 1]);
        }

        float hold[8];
        #pragma unroll
        for (int q = 0; q < 8; q++) hold[q] = hsh[j * 8 + q];

        float hnew[8];
        #pragma unroll
        for (int q = 0; q < 8; q++) {
            float r = sigmoidf_fast(ir[q] + ar[q] + br);
            float z = sigmoidf_fast(iz[q] + az[q] + bz);
            float n = tanhf_fast(inn[q] + r * (an[q] + bnn));
            hnew[q] = (1.0f - z) * n + z * hold[q];
        }

        __syncthreads();   // all reads of old h done
        *reinterpret_cast<float4*>(hsh + j * 8)     =
            make_float4(hnew[0], hnew[1], hnew[2], hnew[3]);
        *reinterpret_cast<float4*>(hsh + j * 8 + 4) =
            make_float4(hnew[4], hnew[5], hnew[6], hnew[7]);
        if (seq_out) {
            #pragma unroll
            for (int q = 0; q < 8; q++)
                seq_out[((size_t)(b0 + q) * T_ + t) * H_ + j] = hnew[q];
        }
        __syncthreads();   // new h visible
    }

    if (h_out) {
        #pragma unroll
        for (int q = 0; q < 8; q++)
            h_out[(b0 + q) * H_ + j] = hsh[j * 8 + q];
    }
}

// ---------------------------------------------------------------------------
// Head: out[b] = sigmoid(W2 @ relu(W1 @ h[b] + b1) + b2)
// One block (64 threads) per batch row.
// ---------------------------------------------------------------------------
__global__ __launch_bounds__(64)
void head_kernel(const float* __restrict__ h,
                 const float* __restrict__ W1, const float* __restrict__ b1,
                 const float* __restrict__ W2, const float* __restrict__ b2,
                 float* __restrict__ out) {
    __shared__ float hs[128];
    __shared__ float red[2];
    const int b = blockIdx.x;
    const int tid = threadIdx.x;   // 0..63

    hs[tid]      = h[b * 128 + tid];
    hs[tid + 64] = h[b * 128 + 64 + tid];
    __syncthreads();

    float acc = b1[tid];
    #pragma unroll 8
    for (int k = 0; k < 128; k++) acc += W1[tid * 128 + k] * hs[k];
    float v = fmaxf(acc, 0.0f) * W2[tid];

    #pragma unroll
    for (int o = 16; o > 0; o >>= 1) v += __shfl_down_sync(0xffffffffu, v, o);
    if ((tid & 31) == 0) red[tid >> 5] = v;
    __syncthreads();
    if (tid == 0) {
        float s = red[0] + red[1] + b2[0];
        out[b] = 1.0f / (1.0f + expf(-s));
    }
}

// ---------------------------------------------------------------------------
// Launch
// ---------------------------------------------------------------------------
extern "C" void kernel_launch(void* const* d_in, const int* in_sizes, int n_in,
                              void* d_out, int out_size) {
    const float* x     = (const float*)d_in[0];
    const float* W_ih0 = (const float*)d_in[1];
    const float* W_hh0 = (const float*)d_in[2];
    const float* b_ih0 = (const float*)d_in[3];
    const float* b_hh0 = (const float*)d_in[4];
    const float* W_ih1 = (const float*)d_in[5];
    const float* W_hh1 = (const float*)d_in[6];
    const float* b_ih1 = (const float*)d_in[7];
    const float* b_hh1 = (const float*)d_in[8];
    const float* W1    = (const float*)d_in[9];
    const float* b1    = (const float*)d_in[10];
    const float* W2    = (const float*)d_in[11];
    const float* b2    = (const float*)d_in[12];
    float* out = (float*)d_out;

    void *gi_p, *seq_p, *hl_p;
    cudaGetSymbolAddress(&gi_p, g_gi);
    cudaGetSymbolAddress(&seq_p, g_seq);
    cudaGetSymbolAddress(&hl_p, g_hlast);
    float* gi    = (float*)gi_p;
    float* seq   = (float*)seq_p;
    float* hlast = (float*)hl_p;

    cudaFuncSetAttribute((const void*)gru_scan_kernel,
                         cudaFuncAttributeMaxDynamicSharedMemorySize, SCAN_SMEM);

    dim3 gemm_grid(BT_ / 128, G_ / 128);

    // Layer 0: input projection, then recurrent scan (produces full sequence)
    sgemm_bias_kernel<<<gemm_grid, 256>>>(x, W_ih0, b_ih0, gi, BT_, G_, I_);
    gru_scan_kernel<<<B_ / 8, 128, SCAN_SMEM>>>(gi, W_hh0, b_hh0, seq, nullptr);

    // Layer 1: input projection on layer-0 sequence, then scan (last hidden only)
    sgemm_bias_kernel<<<gemm_grid, 256>>>(seq, W_ih1, b_ih1, gi, BT_, G_, H_);
    gru_scan_kernel<<<B_ / 8, 128, SCAN_SMEM>>>(gi, W_hh1, b_hh1, nullptr, hlast);

    // Head
    head_kernel<<<B_, 64>>>(hlast, W1, b1, W2, b2, out);
}

// round 8
// speedup vs baseline: 1.0020x; 1.0007x over previous
#include <cuda_runtime.h>
#include <math.h>

// Problem constants
#define B_  1024
#define T_  256
#define I_  153
#define H_  128
#define G_  384           // 3*H
#define BT_ (B_ * T_)

// ---------------------------------------------------------------------------
// Scratch (static device globals; no runtime allocation allowed)
// ---------------------------------------------------------------------------
__device__ float g_gi[(size_t)BT_ * G_];    // gate input projections (reused for both layers)
__device__ float g_seq[(size_t)BT_ * H_];   // layer-0 output sequence
__device__ float g_hlast[B_ * H_];          // layer-1 final hidden state

typedef unsigned long long u64;

// ---------------------------------------------------------------------------
// Packed f32x2 helpers (Blackwell sm_103a): 2 fp32 FMAs per instruction
// ---------------------------------------------------------------------------
__device__ __forceinline__ u64 pack2(float lo, float hi) {
    u64 r;
    asm("mov.b64 %0, {%1, %2};" : "=l"(r) : "f"(lo), "f"(hi));
    return r;
}
__device__ __forceinline__ void unpack2(u64 v, float& lo, float& hi) {
    asm("mov.b64 {%0, %1}, %2;" : "=f"(lo), "=f"(hi) : "l"(v));
}
__device__ __forceinline__ u64 ffma2(u64 a, u64 b, u64 c) {
    u64 d;
    asm("fma.rn.f32x2 %0, %1, %2, %3;" : "=l"(d) : "l"(a), "l"(b), "l"(c));
    return d;
}

__device__ __forceinline__ float sigmoidf_fast(float x) {
    return 1.0f / (1.0f + __expf(-x));
}
__device__ __forceinline__ float tanhf_fast(float x) {
    // tanh(x) = 2/(1+e^{-2x}) - 1 ; graceful saturation at |x| large
    return fmaf(2.0f, 1.0f / (1.0f + __expf(-2.0f * x)), -1.0f);
}

// ---------------------------------------------------------------------------
// GEMM with bias: C[M,N] = A[M,K] @ W[N,K]^T + bias[N]
// 128x128 tile, BK=16, double-buffered SMEM, 256 threads, 8x8 microtile
// via FFMA2 (pairs over N). M%128==0, N%128==0. K arbitrary.
// ---------------------------------------------------------------------------
#define BKG 16

__global__ __launch_bounds__(256, 2)
void sgemm_bias_kernel(const float* __restrict__ A,
                       const float* __restrict__ W,
                       const float* __restrict__ bias,
                       float* __restrict__ C,
                       int M, int N, int K) {
    __shared__ float As[2][BKG][128];
    __shared__ float Bs[2][BKG][128];

    const int bm = blockIdx.x * 128;
    const int bn = blockIdx.y * 128;
    const int tid = threadIdx.x;
    const int tx = tid & 15;       // 8 columns each
    const int ty = tid >> 4;       // 8 rows each

    const int KT = (K + BKG - 1) / BKG;

    u64 acc2[8][4] = {};           // 8 rows x 4 f32x2 pairs (=8 cols)

    // Prologue: load tile 0 into buffer 0
    #pragma unroll
    for (int i = 0; i < 8; i++) {
        int idx = tid + i * 256;           // 0..2047
        int m = idx >> 4;
        int k = idx & 15;
        As[0][k][m] = (k < K) ? A[(size_t)(bm + m) * K + k] : 0.0f;
        Bs[0][k][m] = (k < K) ? W[(size_t)(bn + m) * K + k] : 0.0f;
    }
    __syncthreads();

    int buf = 0;
    for (int kt = 0; kt < KT; kt++) {
        float a_pf[8], b_pf[8];
        const bool has_next = (kt + 1 < KT);
        if (has_next) {
            int kbase = (kt + 1) * BKG;
            #pragma unroll
            for (int i = 0; i < 8; i++) {
                int idx = tid + i * 256;
                int m = idx >> 4;
                int k = idx & 15;
                a_pf[i] = (kbase + k < K) ? A[(size_t)(bm + m) * K + kbase + k] : 0.0f;
                b_pf[i] = (kbase + k < K) ? W[(size_t)(bn + m) * K + kbase + k] : 0.0f;
            }
        }

        #pragma unroll
        for (int k = 0; k < BKG; k++) {
            float4 aLo = *reinterpret_cast<const float4*>(&As[buf][k][ty * 8]);
            float4 aHi = *reinterpret_cast<const float4*>(&As[buf][k][ty * 8 + 4]);
            float a[8] = {aLo.x, aLo.y, aLo.z, aLo.w, aHi.x, aHi.y, aHi.z, aHi.w};
            ulonglong2 b01 = *reinterpret_cast<const ulonglong2*>(&Bs[buf][k][tx * 8]);
            ulonglong2 b23 = *reinterpret_cast<const ulonglong2*>(&Bs[buf][k][tx * 8 + 4]);
            u64 bb[4] = {b01.x, b01.y, b23.x, b23.y};
            #pragma unroll
            for (int i = 0; i < 8; i++) {
                u64 ai = pack2(a[i], a[i]);
                #pragma unroll
                for (int jj = 0; jj < 4; jj++)
                    acc2[i][jj] = ffma2(ai, bb[jj], acc2[i][jj]);
            }
        }

        if (has_next) {
            #pragma unroll
            for (int i = 0; i < 8; i++) {
                int idx = tid + i * 256;
                int m = idx >> 4;
                int k = idx & 15;
                As[buf ^ 1][k][m] = a_pf[i];
                Bs[buf ^ 1][k][m] = b_pf[i];
            }
            __syncthreads();
            buf ^= 1;
        }
    }

    // Store with bias
    #pragma unroll
    for (int i = 0; i < 8; i++) {
        int m = bm + ty * 8 + i;
        size_t row = (size_t)m * N + bn + tx * 8;
        #pragma unroll
        for (int jj = 0; jj < 4; jj++) {
            float c0, c1;
            unpack2(acc2[i][jj], c0, c1);
            int n = bn + tx * 8 + jj * 2;
            C[row + jj * 2]     = c0 + bias[n];
            C[row + jj * 2 + 1] = c1 + bias[n + 1];
        }
    }
}

// ---------------------------------------------------------------------------
// GRU recurrent scan. One CTA = 8 batch rows, 128 threads (4 warps).
// Each thread owns hidden index j = tid and ALL 8 batch rows -> every weight
// LDS (128B full wavefront) feeds 8 batch FMAs. h reads are warp broadcasts.
// W_hh resident in SMEM, transposed with stride padded to 385 (conflict-free
// transpose store; coalesced global read). SMEM = 128*385*4 + 128*8*4 ~ 197KB.
// ---------------------------------------------------------------------------
#define WSTR_ (G_ + 1)
#define SCAN_SMEM ((H_ * WSTR_ + H_ * 8) * 4)

__global__ __launch_bounds__(128, 1)
void gru_scan_kernel(const float* __restrict__ gi,     // [B, T, 384]
                     const float* __restrict__ W_hh,   // [384, 128]
                     const float* __restrict__ b_hh,   // [384]
                     float* __restrict__ seq_out,      // [B, T, 128] or null
                     float* __restrict__ h_out) {      // [B, 128] or null
    extern __shared__ float sm[];
    float* Wsh = sm;                 // [128][385]: Wsh[k*385 + g]
    float* hsh = sm + H_ * WSTR_;    // [128][8]:   hsh[k*8 + b]

    const int j  = threadIdx.x;      // 0..127
    const int b0 = blockIdx.x * 8;

    // Coalesced global read, conflict-free transposed SMEM store (stride 385)
    for (int idx = j; idx < G_ * H_; idx += 128) {
        int g = idx >> 7;            // 0..383
        int k = idx & 127;
        Wsh[k * WSTR_ + g] = W_hh[idx];
    }
    #pragma unroll
    for (int q = 0; q < 8; q++) hsh[j * 8 + q] = 0.0f;

    const float br  = b_hh[j];
    const float bz  = b_hh[H_ + j];
    const float bnn = b_hh[2 * H_ + j];
    __syncthreads();

    const float* wp = Wsh + j;

    for (int t = 0; t < T_; t++) {
        // Prefetch this step's gate inputs for all 8 batch rows (coalesced over j)
        float ir[8], iz[8], inn[8];
        #pragma unroll
        for (int q = 0; q < 8; q++) {
            const float* gp = gi + ((size_t)(b0 + q) * T_ + t) * G_;
            ir[q]  = gp[j];
            iz[q]  = gp[H_ + j];
            inn[q] = gp[2 * H_ + j];
        }

        // gh = h @ W_hh^T : 3 gates x 8 batch via packed f32x2 FMAs
        u64 ar2[4] = {}, az2[4] = {}, an2[4] = {};
        #pragma unroll 4
        for (int k = 0; k < H_; k++) {
            const float* hb = hsh + k * 8;
            ulonglong2 h01 = *reinterpret_cast<const ulonglong2*>(hb);      // batch 0..3
            ulonglong2 h23 = *reinterpret_cast<const ulonglong2*>(hb + 4);  // batch 4..7
            const float* wk = wp + k * WSTR_;
            float wr = wk[0];
            float wz = wk[H_];
            float wn = wk[2 * H_];
            u64 wr2 = pack2(wr, wr);
            u64 wz2 = pack2(wz, wz);
            u64 wn2 = pack2(wn, wn);
            ar2[0] = ffma2(wr2, h01.x, ar2[0]);
            ar2[1] = ffma2(wr2, h01.y, ar2[1]);
            ar2[2] = ffma2(wr2, h23.x, ar2[2]);
            ar2[3] = ffma2(wr2, h23.y, ar2[3]);
            az2[0] = ffma2(wz2, h01.x, az2[0]);
            az2[1] = ffma2(wz2, h01.y, az2[1]);
            az2[2] = ffma2(wz2, h23.x, az2[2]);
            az2[3] = ffma2(wz2, h23.y, az2[3]);
            an2[0] = ffma2(wn2, h01.x, an2[0]);
            an2[1] = ffma2(wn2, h01.y, an2[1]);
            an2[2] = ffma2(wn2, h23.x, an2[2]);
            an2[3] = ffma2(wn2, h23.y, an2[3]);
        }
        float ar[8], az[8], an[8];
        #pragma unroll
        for (int p = 0; p < 4; p++) {
            unpack2(ar2[p], ar[2 * p], ar[2 * p + 1]);
            unpack2(az2[p], az[2 * p], az[2 * p + 1]);
            unpack2(an2[p], an[2 * p], an[2 * p + 1]);
        }

        float hold[8];
        #pragma unroll
        for (int q = 0; q < 8; q++) hold[q] = hsh[j * 8 + q];

        float hnew[8];
        #pragma unroll
        for (int q = 0; q < 8; q++) {
            float r = sigmoidf_fast(ir[q] + ar[q] + br);
            float z = sigmoidf_fast(iz[q] + az[q] + bz);
            float n = tanhf_fast(inn[q] + r * (an[q] + bnn));
            hnew[q] = (1.0f - z) * n + z * hold[q];
        }

        __syncthreads();   // all reads of old h done
        *reinterpret_cast<float4*>(hsh + j * 8)     =
            make_float4(hnew[0], hnew[1], hnew[2], hnew[3]);
        *reinterpret_cast<float4*>(hsh + j * 8 + 4) =
            make_float4(hnew[4], hnew[5], hnew[6], hnew[7]);
        if (seq_out) {
            #pragma unroll
            for (int q = 0; q < 8; q++)
                seq_out[((size_t)(b0 + q) * T_ + t) * H_ + j] = hnew[q];
        }
        __syncthreads();   // new h visible
    }

    if (h_out) {
        #pragma unroll
        for (int q = 0; q < 8; q++)
            h_out[(b0 + q) * H_ + j] = hsh[j * 8 + q];
    }
}

// ---------------------------------------------------------------------------
// Head: out[b] = sigmoid(W2 @ relu(W1 @ h[b] + b1) + b2)
// One block (64 threads) per batch row.
// ---------------------------------------------------------------------------
__global__ __launch_bounds__(64)
void head_kernel(const float* __restrict__ h,
                 const float* __restrict__ W1, const float* __restrict__ b1,
                 const float* __restrict__ W2, const float* __restrict__ b2,
                 float* __restrict__ out) {
    __shared__ float hs[128];
    __shared__ float red[2];
    const int b = blockIdx.x;
    const int tid = threadIdx.x;   // 0..63

    hs[tid]      = h[b * 128 + tid];
    hs[tid + 64] = h[b * 128 + 64 + tid];
    __syncthreads();

    float acc = b1[tid];
    #pragma unroll 8
    for (int k = 0; k < 128; k++) acc += W1[tid * 128 + k] * hs[k];
    float v = fmaxf(acc, 0.0f) * W2[tid];

    #pragma unroll
    for (int o = 16; o > 0; o >>= 1) v += __shfl_down_sync(0xffffffffu, v, o);
    if ((tid & 31) == 0) red[tid >> 5] = v;
    __syncthreads();
    if (tid == 0) {
        float s = red[0] + red[1] + b2[0];
        out[b] = 1.0f / (1.0f + expf(-s));
    }
}

// ---------------------------------------------------------------------------
// Launch
// ---------------------------------------------------------------------------
extern "C" void kernel_launch(void* const* d_in, const int* in_sizes, int n_in,
                              void* d_out, int out_size) {
    const float* x     = (const float*)d_in[0];
    const float* W_ih0 = (const float*)d_in[1];
    const float* W_hh0 = (const float*)d_in[2];
    const float* b_ih0 = (const float*)d_in[3];
    const float* b_hh0 = (const float*)d_in[4];
    const float* W_ih1 = (const float*)d_in[5];
    const float* W_hh1 = (const float*)d_in[6];
    const float* b_ih1 = (const float*)d_in[7];
    const float* b_hh1 = (const float*)d_in[8];
    const float* W1    = (const float*)d_in[9];
    const float* b1    = (const float*)d_in[10];
    const float* W2    = (const float*)d_in[11];
    const float* b2    = (const float*)d_in[12];
    float* out = (float*)d_out;

    void *gi_p, *seq_p, *hl_p;
    cudaGetSymbolAddress(&gi_p, g_gi);
    cudaGetSymbolAddress(&seq_p, g_seq);
    cudaGetSymbolAddress(&hl_p, g_hlast);
    float* gi    = (float*)gi_p;
    float* seq   = (float*)seq_p;
    float* hlast = (float*)hl_p;

    cudaFuncSetAttribute((const void*)gru_scan_kernel,
                         cudaFuncAttributeMaxDynamicSharedMemorySize, SCAN_SMEM);

    dim3 gemm_grid(BT_ / 128, G_ / 128);

    // Layer 0: input projection, then recurrent scan (produces full sequence)
    sgemm_bias_kernel<<<gemm_grid, 256>>>(x, W_ih0, b_ih0, gi, BT_, G_, I_);
    gru_scan_kernel<<<B_ / 8, 128, SCAN_SMEM>>>(gi, W_hh0, b_hh0, seq, nullptr);

    // Layer 1: input projection on layer-0 sequence, then scan (last hidden only)
    sgemm_bias_kernel<<<gemm_grid, 256>>>(seq, W_ih1, b_ih1, gi, BT_, G_, H_);
    gru_scan_kernel<<<B_ / 8, 128, SCAN_SMEM>>>(gi, W_hh1, b_hh1, nullptr, hlast);

    // Head
    head_kernel<<<B_, 64>>>(hlast, W1, b1, W2, b2, out);
}